// round 4
// baseline (speedup 1.0000x reference)
#include <cuda_runtime.h>
#include <cstdint>
#include <cstddef>

#define T_SEQ 512
#define BATCH 64
#define DIN   256
#define HID   1024
#define NCTA  128

// ---------------- static scratch (no allocations) ----------------
__device__ __align__(16) float g_xg[(size_t)T_SEQ * BATCH * 4096];   // [t][b][4H]
__device__ __align__(16) float g_seq0[(size_t)T_SEQ * BATCH * HID];  // [t][b][k]
__device__ __align__(16) float g_h[2][HID * BATCH];                  // [k][b] ping-pong
__device__ unsigned g_bar;

// ---------------- helpers ----------------
__device__ __forceinline__ float f2tf(float f) {
    uint32_t u; asm("cvt.rna.tf32.f32 %0, %1;" : "=r"(u) : "f"(f));
    return __uint_as_float(u);
}

__device__ __forceinline__ void mma_tf32(float c[4], const uint32_t a[4], const uint32_t b[2]) {
    asm volatile(
        "mma.sync.aligned.m16n8k8.row.col.f32.tf32.tf32.f32 "
        "{%0,%1,%2,%3}, {%4,%5,%6,%7}, {%8,%9}, {%0,%1,%2,%3};"
        : "+f"(c[0]), "+f"(c[1]), "+f"(c[2]), "+f"(c[3])
        : "r"(a[0]), "r"(a[1]), "r"(a[2]), "r"(a[3]), "r"(b[0]), "r"(b[1]));
}

// ---------------- reset: zero h ping-pong + grid barrier ----------------
__global__ void reset_kernel() {
    int tid = blockIdx.x * blockDim.x + threadIdx.x;
    float* hb = (float*)g_h;
    for (int i = tid; i < 2 * HID * BATCH; i += gridDim.x * blockDim.x) hb[i] = 0.0f;
    if (tid == 0) g_bar = 0u;
}

// ---------------- xg GEMM: g_xg[t][b][n] = A_row(t,b) . W[n][:] + bias[n] ----------------
// AMODE 0: A = x [B][T][D]      (row m=b -> x[(b*T+t)*D + k]),     K = DIN
// AMODE 1: A = g_seq0 [T][B][H] (row m=b -> seq0[(t*B+b)*H + k]),  K = HID
template<int AMODE>
__global__ __launch_bounds__(256) void gemm_xg(
    const float* __restrict__ A, const float* __restrict__ W,
    const float* __restrict__ bias, int K)
{
    __shared__ __align__(16) float Ash[64 * 36];
    __shared__ __align__(16) float Bsh[128 * 36];

    const int tid = threadIdx.x, lane = tid & 31, w = tid >> 5;
    const int wm = w & 1, wn = w >> 1;         // 2 x 4 warp grid
    const int t = blockIdx.y, n0 = blockIdx.x * 128;
    const int g = lane >> 2, tq = lane & 3;

    float acc[2][4][4] = {};

    const int nchunk = K / 32;
    for (int kc = 0; kc < nchunk; kc++) {
        int k0 = kc * 32;
        __syncthreads();
        // stage A: 64 rows x 32 k (as tf32)
        #pragma unroll
        for (int i = 0; i < 2; i++) {
            int fi = tid + i * 256; int r = fi >> 3, k4 = fi & 7;
            const float* src = (AMODE == 0)
                ? (A + ((size_t)r * T_SEQ + t) * DIN + k0 + k4 * 4)
                : (g_seq0 + ((size_t)t * BATCH + r) * HID + k0 + k4 * 4);
            float4 v = *(const float4*)src;
            *(float4*)(Ash + r * 36 + k4 * 4) =
                make_float4(f2tf(v.x), f2tf(v.y), f2tf(v.z), f2tf(v.w));
        }
        // stage B: 128 rows x 32 k
        #pragma unroll
        for (int i = 0; i < 4; i++) {
            int fi = tid + i * 256; int r = fi >> 3, k4 = fi & 7;
            float4 v = *(const float4*)(W + (size_t)(n0 + r) * K + k0 + k4 * 4);
            *(float4*)(Bsh + r * 36 + k4 * 4) =
                make_float4(f2tf(v.x), f2tf(v.y), f2tf(v.z), f2tf(v.w));
        }
        __syncthreads();
        #pragma unroll
        for (int kt = 0; kt < 4; kt++) {
            uint32_t a[2][4];
            #pragma unroll
            for (int am = 0; am < 2; am++) {
                int mb = (wm * 2 + am) * 16;
                a[am][0] = __float_as_uint(Ash[(mb + g) * 36 + kt * 8 + tq]);
                a[am][1] = __float_as_uint(Ash[(mb + 8 + g) * 36 + kt * 8 + tq]);
                a[am][2] = __float_as_uint(Ash[(mb + g) * 36 + kt * 8 + tq + 4]);
                a[am][3] = __float_as_uint(Ash[(mb + 8 + g) * 36 + kt * 8 + tq + 4]);
            }
            #pragma unroll
            for (int c = 0; c < 4; c++) {
                int nb = (wn * 4 + c) * 8;
                uint32_t b[2];
                b[0] = __float_as_uint(Bsh[(nb + g) * 36 + kt * 8 + tq]);
                b[1] = __float_as_uint(Bsh[(nb + g) * 36 + kt * 8 + tq + 4]);
                mma_tf32(acc[0][c], a[0], b);
                mma_tf32(acc[1][c], a[1], b);
            }
        }
    }
    // epilogue: bias + store
    #pragma unroll
    for (int am = 0; am < 2; am++) {
        int m = (wm * 2 + am) * 16 + g;
        #pragma unroll
        for (int c = 0; c < 4; c++) {
            int n = n0 + (wn * 4 + c) * 8 + 2 * tq;
            float2 bi = *(const float2*)(bias + n);
            *(float2*)(g_xg + ((size_t)t * BATCH + m) * 4096 + n) =
                make_float2(acc[am][c][0] + bi.x, acc[am][c][1] + bi.y);
            *(float2*)(g_xg + ((size_t)t * BATCH + m + 8) * 4096 + n) =
                make_float2(acc[am][c][2] + bi.x, acc[am][c][3] + bi.y);
        }
    }
}

// ---------------- persistent LSTM recurrence ----------------
// 128 CTAs, CTA owns 8 hidden units j0..j0+7 (32 Whh rows in SMEM for all steps).
// 32 warps: wm (4 M-tiles of 16) x wn (2 N-groups of 16 rows) x wk (4-way K split).
template<int LAYER>
__global__ __launch_bounds__(1024) void lstm_rec(const float* __restrict__ Whh)
{
    extern __shared__ __align__(16) float sm[];
    float* Wsm = sm;                          // 32 x 1028 (tf32)
    float* Hsm = sm + 32 * 1028;              // 256 x 64, XOR-8 swizzled
    float* Gsm = sm + 32 * 1028 + 256 * 64;   // 64 x 36

    const int tid = threadIdx.x, lane = tid & 31, w = tid >> 5;
    const int g = lane >> 2, tq = lane & 3;
    const int wm = w & 3;                     // 0..3 : M tile
    const int wn = (w >> 2) & 1;              // 0..1 : N group (2 x n8)
    const int wk = w >> 3;                    // 0..3 : K split
    const int j0 = blockIdx.x * 8;

    // load 32 weight rows (r = gate*8 + jj) -> SMEM as tf32, stride 1028 (conflict-free)
    #pragma unroll
    for (int i = 0; i < 8; i++) {
        int fi = tid + i * 1024;              // float4 index 0..8191
        int r = fi >> 8, c4 = fi & 255;
        int gate = r >> 3, jj = r & 7;
        float4 v = *(const float4*)(Whh + (size_t)(gate * HID + j0 + jj) * HID + c4 * 4);
        *(float4*)(Wsm + r * 1028 + c4 * 4) =
            make_float4(f2tf(v.x), f2tf(v.y), f2tf(v.z), f2tf(v.w));
    }

    const int ejj = tid & 7, eb = tid >> 3;   // elementwise mapping (tid < 512)
    float cst = 0.0f;                         // cell state lives in registers
    __syncthreads();

    for (int t = 0; t < T_SEQ; t++) {
        const float* hb = g_h[t & 1];
        float acc[2][4] = {};

        #pragma unroll 1
        for (int ch = 0; ch < 4; ch++) {      // 4 k-chunks of 256
            __syncthreads();
            // stage h chunk [256k][64b], XOR-8 swizzle, L2-coherent loads
            #pragma unroll
            for (int i = 0; i < 4; i++) {
                int fi = tid + i * 1024;      // float4 idx 0..4095
                int kl = fi >> 4, b4 = (fi & 15) * 4;
                float4 v = __ldcg((const float4*)(hb + (ch * 256 + kl) * 64 + b4));
                int sb = b4 ^ (8 * (kl & 3));
                *(float4*)(Hsm + kl * 64 + sb) =
                    make_float4(f2tf(v.x), f2tf(v.y), f2tf(v.z), f2tf(v.w));
            }
            __syncthreads();
            const int X = 8 * tq;
            const int mb = wm * 16;
            #pragma unroll 4
            for (int kt = wk * 8; kt < wk * 8 + 8; kt++) {
                int kk = kt * 8 + tq;
                uint32_t a[4];
                a[0] = __float_as_uint(Hsm[kk * 64 + ((mb + g) ^ X)]);
                a[1] = __float_as_uint(Hsm[kk * 64 + ((mb + 8 + g) ^ X)]);
                a[2] = __float_as_uint(Hsm[(kk + 4) * 64 + ((mb + g) ^ X)]);
                a[3] = __float_as_uint(Hsm[(kk + 4) * 64 + ((mb + 8 + g) ^ X)]);
                int kglob = ch * 256 + kt * 8 + tq;
                #pragma unroll
                for (int c = 0; c < 2; c++) {
                    int r = (wn * 2 + c) * 8 + g;   // 0..31: gate-row
                    uint32_t b[2];
                    b[0] = __float_as_uint(Wsm[r * 1028 + kglob]);
                    b[1] = __float_as_uint(Wsm[r * 1028 + kglob + 4]);
                    mma_tf32(acc[c], a, b);
                }
            }
        }
        // scatter-reduce C fragments across the 4 k-split warps -> Gsm[b][row]
        {
            int m = wm * 16 + g;
            #pragma unroll
            for (int rd = 0; rd < 4; rd++) {
                if (wk == rd) {
                    #pragma unroll
                    for (int c = 0; c < 2; c++) {
                        int n = (wn * 2 + c) * 8 + 2 * tq;
                        float2* p0 = (float2*)(Gsm + m * 36 + n);
                        float2* p1 = (float2*)(Gsm + (m + 8) * 36 + n);
                        if (rd == 0) {
                            *p0 = make_float2(acc[c][0], acc[c][1]);
                            *p1 = make_float2(acc[c][2], acc[c][3]);
                        } else {
                            float2 v0 = *p0, v1 = *p1;
                            *p0 = make_float2(v0.x + acc[c][0], v0.y + acc[c][1]);
                            *p1 = make_float2(v1.x + acc[c][2], v1.y + acc[c][3]);
                        }
                    }
                }
                __syncthreads();
            }
        }
        // elementwise LSTM cell (512 threads: (b, jj))
        if (tid < 512) {
            const float* xg = g_xg + ((size_t)t * BATCH + eb) * 4096 + j0 + ejj;
            float gi = Gsm[eb * 36 + 0 + ejj]  + xg[0];
            float gf = Gsm[eb * 36 + 8 + ejj]  + xg[1024];
            float gg = Gsm[eb * 36 + 16 + ejj] + xg[2048];
            float go = Gsm[eb * 36 + 24 + ejj] + xg[3072];
            gi = 1.0f / (1.0f + __expf(-gi));
            gf = 1.0f / (1.0f + __expf(-gf));
            gg = tanhf(gg);
            go = 1.0f / (1.0f + __expf(-go));
            cst = gf * cst + gi * gg;
            float h = go * tanhf(cst);
            __stcg(&g_h[(t + 1) & 1][(j0 + ejj) * 64 + eb], h);
            if (LAYER == 0)
                __stcg(&g_seq0[((size_t)t * BATCH + eb) * HID + j0 + ejj], h);
        }
        // grid barrier (all 128 CTAs co-resident; CG grid.sync pattern)
        __syncthreads();
        if (tid == 0) {
            __threadfence();
            atomicAdd(&g_bar, 1u);
            unsigned target = (unsigned)(t + 1) * NCTA;
            while (*(volatile unsigned*)&g_bar < target) { }
            __threadfence();
        }
        __syncthreads();
    }
}

// ---------------- fc head: out[b] = h_final[b][:] . Wfc + bfc ----------------
__global__ void fc_kernel(const float* __restrict__ Wfc, const float* __restrict__ bfc,
                          float* __restrict__ out)
{
    __shared__ float red[256];
    int b = blockIdx.x, tid = threadIdx.x;
    float s = 0.0f;
    for (int j = tid; j < HID; j += 256)
        s += g_h[0][j * 64 + b] * Wfc[j];   // final h after t=511 sits in buffer 0
    red[tid] = s; __syncthreads();
    for (int st = 128; st > 0; st >>= 1) {
        if (tid < st) red[tid] += red[tid + st];
        __syncthreads();
    }
    if (tid == 0) out[b] = red[0] + bfc[0];
}

// ---------------- launch ----------------
extern "C" void kernel_launch(void* const* d_in, const int* in_sizes, int n_in,
                              void* d_out, int out_size)
{
    const float* x    = (const float*)d_in[0];
    const float* Wih0 = (const float*)d_in[1];
    const float* Whh0 = (const float*)d_in[2];
    const float* b0   = (const float*)d_in[3];
    const float* Wih1 = (const float*)d_in[4];
    const float* Whh1 = (const float*)d_in[5];
    const float* b1   = (const float*)d_in[6];
    const float* Wfc  = (const float*)d_in[7];
    const float* bfc  = (const float*)d_in[8];
    float* out = (float*)d_out;

    const size_t rec_smem = (size_t)(32 * 1028 + 256 * 64 + 64 * 36) * sizeof(float);
    static int attr_done = 0;
    if (!attr_done) {
        cudaFuncSetAttribute(lstm_rec<0>, cudaFuncAttributeMaxDynamicSharedMemorySize, (int)rec_smem);
        cudaFuncSetAttribute(lstm_rec<1>, cudaFuncAttributeMaxDynamicSharedMemorySize, (int)rec_smem);
        attr_done = 1;
    }

    reset_kernel<<<64, 256>>>();
    gemm_xg<0><<<dim3(32, T_SEQ), 256>>>(x, Wih0, b0, DIN);
    lstm_rec<0><<<NCTA, 1024, rec_smem>>>(Whh0);
    reset_kernel<<<64, 256>>>();
    gemm_xg<1><<<dim3(32, T_SEQ), 256>>>(nullptr, Wih1, b1, HID);
    lstm_rec<1><<<NCTA, 1024, rec_smem>>>(Whh1);
    fc_kernel<<<BATCH, 256>>>(Wfc, bfc, out);
}

// round 5
// speedup vs baseline: 1.1003x; 1.1003x over previous
#include <cuda_runtime.h>
#include <cstdint>
#include <cstddef>

#define T_SEQ 512
#define BATCH 64
#define DIN   256
#define HID   1024
#define NCTA  128

// ---------------- static scratch (no allocations) ----------------
__device__ __align__(16) float g_xg[(size_t)T_SEQ * BATCH * 4096];   // [t][b][4H]
__device__ __align__(16) float g_seq0[(size_t)T_SEQ * BATCH * HID];  // [t][b][k]
__device__ __align__(16) float g_h[2][HID * BATCH];                  // [k][b] ping-pong (tf32 values)
__device__ unsigned g_bar;

// ---------------- helpers ----------------
__device__ __forceinline__ float f2tf(float f) {
    uint32_t u; asm("cvt.rna.tf32.f32 %0, %1;" : "=r"(u) : "f"(f));
    return __uint_as_float(u);
}

__device__ __forceinline__ void mma_tf32(float c[4], const uint32_t a[4], const uint32_t b[2]) {
    asm volatile(
        "mma.sync.aligned.m16n8k8.row.col.f32.tf32.tf32.f32 "
        "{%0,%1,%2,%3}, {%4,%5,%6,%7}, {%8,%9}, {%0,%1,%2,%3};"
        : "+f"(c[0]), "+f"(c[1]), "+f"(c[2]), "+f"(c[3])
        : "r"(a[0]), "r"(a[1]), "r"(a[2]), "r"(a[3]), "r"(b[0]), "r"(b[1]));
}

// ---------------- reset: zero h ping-pong + grid barrier ----------------
__global__ void reset_kernel() {
    int tid = blockIdx.x * blockDim.x + threadIdx.x;
    float* hb = (float*)g_h;
    for (int i = tid; i < 2 * HID * BATCH; i += gridDim.x * blockDim.x) hb[i] = 0.0f;
    if (tid == 0) g_bar = 0u;
}

// ---------------- xg GEMM: g_xg[t][b][n] = A_row(t,b) . W[n][:] + bias[n] ----------------
// AMODE 0: A = x [B][T][D]      (row m=b -> x[(b*T+t)*D + k]),     K = DIN
// AMODE 1: A = g_seq0 [T][B][H] (row m=b -> seq0[(t*B+b)*H + k]),  K = HID
template<int AMODE>
__global__ __launch_bounds__(256) void gemm_xg(
    const float* __restrict__ A, const float* __restrict__ W,
    const float* __restrict__ bias, int K)
{
    __shared__ __align__(16) float Ash[64 * 36];
    __shared__ __align__(16) float Bsh[128 * 36];

    const int tid = threadIdx.x, lane = tid & 31, w = tid >> 5;
    const int wm = w & 1, wn = w >> 1;         // 2 x 4 warp grid
    const int t = blockIdx.y, n0 = blockIdx.x * 128;
    const int g = lane >> 2, tq = lane & 3;

    float acc[2][4][4] = {};

    const int nchunk = K / 32;
    for (int kc = 0; kc < nchunk; kc++) {
        int k0 = kc * 32;
        __syncthreads();
        // stage A: 64 rows x 32 k (as tf32)
        #pragma unroll
        for (int i = 0; i < 2; i++) {
            int fi = tid + i * 256; int r = fi >> 3, k4 = fi & 7;
            const float* src = (AMODE == 0)
                ? (A + ((size_t)r * T_SEQ + t) * DIN + k0 + k4 * 4)
                : (g_seq0 + ((size_t)t * BATCH + r) * HID + k0 + k4 * 4);
            float4 v = *(const float4*)src;
            *(float4*)(Ash + r * 36 + k4 * 4) =
                make_float4(f2tf(v.x), f2tf(v.y), f2tf(v.z), f2tf(v.w));
        }
        // stage B: 128 rows x 32 k
        #pragma unroll
        for (int i = 0; i < 4; i++) {
            int fi = tid + i * 256; int r = fi >> 3, k4 = fi & 7;
            float4 v = *(const float4*)(W + (size_t)(n0 + r) * K + k0 + k4 * 4);
            *(float4*)(Bsh + r * 36 + k4 * 4) =
                make_float4(f2tf(v.x), f2tf(v.y), f2tf(v.z), f2tf(v.w));
        }
        __syncthreads();
        #pragma unroll
        for (int kt = 0; kt < 4; kt++) {
            uint32_t a[2][4];
            #pragma unroll
            for (int am = 0; am < 2; am++) {
                int mb = (wm * 2 + am) * 16;
                a[am][0] = __float_as_uint(Ash[(mb + g) * 36 + kt * 8 + tq]);
                a[am][1] = __float_as_uint(Ash[(mb + 8 + g) * 36 + kt * 8 + tq]);
                a[am][2] = __float_as_uint(Ash[(mb + g) * 36 + kt * 8 + tq + 4]);
                a[am][3] = __float_as_uint(Ash[(mb + 8 + g) * 36 + kt * 8 + tq + 4]);
            }
            #pragma unroll
            for (int c = 0; c < 4; c++) {
                int nb = (wn * 4 + c) * 8;
                uint32_t b[2];
                b[0] = __float_as_uint(Bsh[(nb + g) * 36 + kt * 8 + tq]);
                b[1] = __float_as_uint(Bsh[(nb + g) * 36 + kt * 8 + tq + 4]);
                mma_tf32(acc[0][c], a[0], b);
                mma_tf32(acc[1][c], a[1], b);
            }
        }
    }
    // epilogue: bias + store
    #pragma unroll
    for (int am = 0; am < 2; am++) {
        int m = (wm * 2 + am) * 16 + g;
        #pragma unroll
        for (int c = 0; c < 4; c++) {
            int n = n0 + (wn * 4 + c) * 8 + 2 * tq;
            float2 bi = *(const float2*)(bias + n);
            *(float2*)(g_xg + ((size_t)t * BATCH + m) * 4096 + n) =
                make_float2(acc[am][c][0] + bi.x, acc[am][c][1] + bi.y);
            *(float2*)(g_xg + ((size_t)t * BATCH + m + 8) * 4096 + n) =
                make_float2(acc[am][c][2] + bi.x, acc[am][c][3] + bi.y);
        }
    }
}

// ---------------- persistent LSTM recurrence ----------------
// 128 CTAs x 512 threads. CTA owns 8 hidden units j0..j0+7 (32 Whh rows in SMEM all steps).
// 16 warps = wm(2: batch 32-halves) x wk(8: k-split). Each warp: Mt=2 m16-tiles, all 4 n8-tiles.
// A-fragments (h) loaded DIRECTLY from L2 (__ldcg, h stored as tf32) — no SMEM staging.
template<int LAYER>
__global__ __launch_bounds__(512) void lstm_rec(const float* __restrict__ Whh)
{
    extern __shared__ __align__(16) float sm[];
    float* Wsm = sm;                 // 32 x 1028 (tf32)
    float* Gsm = sm + 32 * 1028;     // 2 slices x 64 x 36

    const int tid = threadIdx.x, lane = tid & 31, w = tid >> 5;
    const int g = lane >> 2, tq = lane & 3;
    const int wm = w & 1;            // batch half: cols wm*32 .. +31
    const int wk = w >> 1;           // 0..7 : k-split (16 kt each)
    const int j0 = blockIdx.x * 8;

    // load 32 weight rows (r = gate*8 + jj) -> SMEM as tf32, stride 1028 (conflict-free)
    #pragma unroll
    for (int i = 0; i < 16; i++) {
        int fi = tid + i * 512;               // float4 index 0..8191
        int r = fi >> 8, c4 = fi & 255;
        int gate = r >> 3, jj = r & 7;
        float4 v = *(const float4*)(Whh + (size_t)(gate * HID + j0 + jj) * HID + c4 * 4);
        *(float4*)(Wsm + r * 1028 + c4 * 4) =
            make_float4(f2tf(v.x), f2tf(v.y), f2tf(v.z), f2tf(v.w));
    }

    const int ejj = tid & 7, eb = tid >> 3;   // elementwise mapping: all 512 threads
    float cst = 0.0f;                         // cell state in registers
    __syncthreads();

    for (int t = 0; t < T_SEQ; t++) {
        const float* hb = g_h[t & 1];
        float acc[2][4][4] = {};

        #pragma unroll 4
        for (int i = 0; i < 16; i++) {
            int kt = wk * 16 + i;             // 0..127
            int kk = kt * 8 + tq;             // k row (of 1024)
            uint32_t a[2][4];
            #pragma unroll
            for (int am = 0; am < 2; am++) {
                int mb = wm * 32 + am * 16;
                a[am][0] = __float_as_uint(__ldcg(hb + (size_t)kk * 64 + mb + g));
                a[am][1] = __float_as_uint(__ldcg(hb + (size_t)kk * 64 + mb + 8 + g));
                a[am][2] = __float_as_uint(__ldcg(hb + (size_t)(kk + 4) * 64 + mb + g));
                a[am][3] = __float_as_uint(__ldcg(hb + (size_t)(kk + 4) * 64 + mb + 8 + g));
            }
            #pragma unroll
            for (int c = 0; c < 4; c++) {
                int r = c * 8 + g;            // gate-row 0..31
                uint32_t b[2];
                b[0] = __float_as_uint(Wsm[r * 1028 + kk]);
                b[1] = __float_as_uint(Wsm[r * 1028 + kk + 4]);
                mma_tf32(acc[0][c], a[0], b);
                mma_tf32(acc[1][c], a[1], b);
            }
        }

        // reduce 8 k-partials: 2 Gsm slices (s = wk&1), 4 serialized rounds (rd = wk>>1)
        #pragma unroll
        for (int rd = 0; rd < 4; rd++) {
            if ((wk >> 1) == rd) {
                float* Gs = Gsm + (wk & 1) * (64 * 36);
                #pragma unroll
                for (int am = 0; am < 2; am++) {
                    int m = wm * 32 + am * 16 + g;
                    #pragma unroll
                    for (int c = 0; c < 4; c++) {
                        int n = c * 8 + 2 * tq;
                        float2* p0 = (float2*)(Gs + m * 36 + n);
                        float2* p1 = (float2*)(Gs + (m + 8) * 36 + n);
                        if (rd == 0) {
                            *p0 = make_float2(acc[am][c][0], acc[am][c][1]);
                            *p1 = make_float2(acc[am][c][2], acc[am][c][3]);
                        } else {
                            float2 v0 = *p0, v1 = *p1;
                            *p0 = make_float2(v0.x + acc[am][c][0], v0.y + acc[am][c][1]);
                            *p1 = make_float2(v1.x + acc[am][c][2], v1.y + acc[am][c][3]);
                        }
                    }
                }
            }
            __syncthreads();
        }

        // elementwise LSTM cell: thread = (b=eb, jj=ejj)
        {
            const float* xg = g_xg + ((size_t)t * BATCH + eb) * 4096 + j0 + ejj;
            const float* G0 = Gsm;
            const float* G1 = Gsm + 64 * 36;
            int gb = eb * 36 + ejj;
            float gi = G0[gb]      + G1[gb]      + xg[0];
            float gf = G0[gb + 8]  + G1[gb + 8]  + xg[1024];
            float gg = G0[gb + 16] + G1[gb + 16] + xg[2048];
            float go = G0[gb + 24] + G1[gb + 24] + xg[3072];
            gi = 1.0f / (1.0f + __expf(-gi));
            gf = 1.0f / (1.0f + __expf(-gf));
            gg = tanhf(gg);
            go = 1.0f / (1.0f + __expf(-go));
            cst = gf * cst + gi * gg;
            float h = go * tanhf(cst);
            // h published as tf32 (mma reads it raw; saves consumer-side cvt)
            __stcg(&g_h[(t + 1) & 1][(j0 + ejj) * 64 + eb], f2tf(h));
            if (LAYER == 0)
                __stcg(&g_seq0[((size_t)t * BATCH + eb) * HID + j0 + ejj], h);
        }

        // grid barrier (all 128 CTAs co-resident)
        __syncthreads();
        if (tid == 0) {
            __threadfence();
            atomicAdd(&g_bar, 1u);
            unsigned target = (unsigned)(t + 1) * NCTA;
            while (*(volatile unsigned*)&g_bar < target) { }
            __threadfence();
        }
        __syncthreads();
    }
}

// ---------------- fc head: out[b] = h_final[b][:] . Wfc + bfc ----------------
__global__ void fc_kernel(const float* __restrict__ Wfc, const float* __restrict__ bfc,
                          float* __restrict__ out)
{
    __shared__ float red[256];
    int b = blockIdx.x, tid = threadIdx.x;
    float s = 0.0f;
    for (int j = tid; j < HID; j += 256)
        s += g_h[0][j * 64 + b] * Wfc[j];   // final h after t=511 sits in buffer 0
    red[tid] = s; __syncthreads();
    for (int st = 128; st > 0; st >>= 1) {
        if (tid < st) red[tid] += red[tid + st];
        __syncthreads();
    }
    if (tid == 0) out[b] = red[0] + bfc[0];
}

// ---------------- launch ----------------
extern "C" void kernel_launch(void* const* d_in, const int* in_sizes, int n_in,
                              void* d_out, int out_size)
{
    const float* x    = (const float*)d_in[0];
    const float* Wih0 = (const float*)d_in[1];
    const float* Whh0 = (const float*)d_in[2];
    const float* b0   = (const float*)d_in[3];
    const float* Wih1 = (const float*)d_in[4];
    const float* Whh1 = (const float*)d_in[5];
    const float* b1   = (const float*)d_in[6];
    const float* Wfc  = (const float*)d_in[7];
    const float* bfc  = (const float*)d_in[8];
    float* out = (float*)d_out;

    const size_t rec_smem = (size_t)(32 * 1028 + 2 * 64 * 36) * sizeof(float);
    static int attr_done = 0;
    if (!attr_done) {
        cudaFuncSetAttribute(lstm_rec<0>, cudaFuncAttributeMaxDynamicSharedMemorySize, (int)rec_smem);
        cudaFuncSetAttribute(lstm_rec<1>, cudaFuncAttributeMaxDynamicSharedMemorySize, (int)rec_smem);
        attr_done = 1;
    }

    reset_kernel<<<64, 256>>>();
    gemm_xg<0><<<dim3(32, T_SEQ), 256>>>(x, Wih0, b0, DIN);
    lstm_rec<0><<<NCTA, 512, rec_smem>>>(Whh0);
    reset_kernel<<<64, 256>>>();
    gemm_xg<1><<<dim3(32, T_SEQ), 256>>>(nullptr, Wih1, b1, HID);
    lstm_rec<1><<<NCTA, 512, rec_smem>>>(Whh1);
    fc_kernel<<<BATCH, 256>>>(Wfc, bfc, out);
}

// round 10
// speedup vs baseline: 1.3871x; 1.2607x over previous
#include <cuda_runtime.h>
#include <cstdint>
#include <cstddef>

#define T_SEQ 512
#define BATCH 64
#define DIN   256
#define HID   1024
#define NCTA  128

// ---------------- static scratch (no allocations) ----------------
__device__ __align__(16) float g_xg[(size_t)T_SEQ * BATCH * 4096];   // [t][b][4H]
__device__ __align__(16) float g_seq0[(size_t)T_SEQ * BATCH * HID];  // [t][b][k]
// h ping-pong in mma-FRAGMENT order (tf32 values):
// index = kt*512 + half*256 + m*4 + tq   (k = kt*8 + half*4 + tq, m = batch)
__device__ __align__(16) float g_hfrag[2][HID / 8 * 512];            // 2 x 65536 floats
__device__ unsigned g_bar;

// ---------------- helpers ----------------
__device__ __forceinline__ float f2tf(float f) {
    uint32_t u; asm("cvt.rna.tf32.f32 %0, %1;" : "=r"(u) : "f"(f));
    return __uint_as_float(u);
}

__device__ __forceinline__ void mma_tf32(float c[4], const uint32_t a[4], const uint32_t b[2]) {
    asm volatile(
        "mma.sync.aligned.m16n8k8.row.col.f32.tf32.tf32.f32 "
        "{%0,%1,%2,%3}, {%4,%5,%6,%7}, {%8,%9}, {%0,%1,%2,%3};"
        : "+f"(c[0]), "+f"(c[1]), "+f"(c[2]), "+f"(c[3])
        : "r"(a[0]), "r"(a[1]), "r"(a[2]), "r"(a[3]), "r"(b[0]), "r"(b[1]));
}

// ---------------- reset: zero h ping-pong + grid barrier ----------------
__global__ void reset_kernel() {
    int tid = blockIdx.x * blockDim.x + threadIdx.x;
    float* hb = (float*)g_hfrag;
    for (int i = tid; i < 2 * (HID / 8) * 512; i += gridDim.x * blockDim.x) hb[i] = 0.0f;
    if (tid == 0) g_bar = 0u;
}

// ---------------- xg GEMM (M=128: 2 timesteps per CTA) ----------------
// g_xg[t][b][n] = A_row(t,b) . W[n][:] + bias[n]
// AMODE 0: A = x [B][T][D]      (row -> x[(b*T+t)*D + k]),      K = DIN
// AMODE 1: A = g_seq0 [T][B][H] (row -> seq0[(t*B+b)*H + k]),   K = HID
template<int AMODE>
__global__ __launch_bounds__(256) void gemm_xg(
    const float* __restrict__ A, const float* __restrict__ W,
    const float* __restrict__ bias, int K)
{
    __shared__ __align__(16) float Ash[128 * 36];
    __shared__ __align__(16) float Bsh[128 * 36];

    const int tid = threadIdx.x, lane = tid & 31, w = tid >> 5;
    const int wm = w & 1, wn = w >> 1;          // 2 x 4 warp grid
    const int t0 = blockIdx.y * 2, n0 = blockIdx.x * 128;
    const int g = lane >> 2, tq = lane & 3;

    float acc[4][4][4] = {};

    const int nchunk = K / 32;
    for (int kc = 0; kc < nchunk; kc++) {
        int k0 = kc * 32;
        __syncthreads();
        // stage A: 128 rows (2 timesteps x 64 batch) x 32 k (as tf32)
        #pragma unroll
        for (int i = 0; i < 4; i++) {
            int fi = tid + i * 256; int r = fi >> 3, k4 = fi & 7;
            int tl = r >> 6, b = r & 63;
            const float* src = (AMODE == 0)
                ? (A + ((size_t)b * T_SEQ + t0 + tl) * DIN + k0 + k4 * 4)
                : (g_seq0 + ((size_t)(t0 + tl) * BATCH + b) * HID + k0 + k4 * 4);
            float4 v = *(const float4*)src;
            *(float4*)(Ash + r * 36 + k4 * 4) =
                make_float4(f2tf(v.x), f2tf(v.y), f2tf(v.z), f2tf(v.w));
        }
        // stage B: 128 rows x 32 k
        #pragma unroll
        for (int i = 0; i < 4; i++) {
            int fi = tid + i * 256; int r = fi >> 3, k4 = fi & 7;
            float4 v = *(const float4*)(W + (size_t)(n0 + r) * K + k0 + k4 * 4);
            *(float4*)(Bsh + r * 36 + k4 * 4) =
                make_float4(f2tf(v.x), f2tf(v.y), f2tf(v.z), f2tf(v.w));
        }
        __syncthreads();
        #pragma unroll
        for (int kt = 0; kt < 4; kt++) {
            uint32_t a[4][4];
            #pragma unroll
            for (int am = 0; am < 4; am++) {
                int mb = wm * 64 + am * 16;
                a[am][0] = __float_as_uint(Ash[(mb + g) * 36 + kt * 8 + tq]);
                a[am][1] = __float_as_uint(Ash[(mb + 8 + g) * 36 + kt * 8 + tq]);
                a[am][2] = __float_as_uint(Ash[(mb + g) * 36 + kt * 8 + tq + 4]);
                a[am][3] = __float_as_uint(Ash[(mb + 8 + g) * 36 + kt * 8 + tq + 4]);
            }
            #pragma unroll
            for (int c = 0; c < 4; c++) {
                int nb = (wn * 4 + c) * 8;
                uint32_t b[2];
                b[0] = __float_as_uint(Bsh[(nb + g) * 36 + kt * 8 + tq]);
                b[1] = __float_as_uint(Bsh[(nb + g) * 36 + kt * 8 + tq + 4]);
                #pragma unroll
                for (int am = 0; am < 4; am++) mma_tf32(acc[am][c], a[am], b);
            }
        }
    }
    // epilogue: bias + store
    #pragma unroll
    for (int am = 0; am < 4; am++) {
        int m = wm * 64 + am * 16 + g;
        int tl = m >> 6, b = m & 63;            // m and m+8 share tl
        #pragma unroll
        for (int c = 0; c < 4; c++) {
            int n = n0 + (wn * 4 + c) * 8 + 2 * tq;
            float2 bi = *(const float2*)(bias + n);
            *(float2*)(g_xg + ((size_t)(t0 + tl) * BATCH + b) * 4096 + n) =
                make_float2(acc[am][c][0] + bi.x, acc[am][c][1] + bi.y);
            *(float2*)(g_xg + ((size_t)(t0 + tl) * BATCH + b + 8) * 4096 + n) =
                make_float2(acc[am][c][2] + bi.x, acc[am][c][3] + bi.y);
        }
    }
}

// ---------------- persistent LSTM recurrence ----------------
// 128 CTAs x 512 threads. CTA owns 8 hidden units j0..j0+7 (32 Whh rows in SMEM).
// 16 warps = wm(2: batch halves) x wk(8: k-split of 16 kt each).
// A-fragments read from g_hfrag (fragment-ordered, tf32): 1 wavefront / 128B per LDG.
template<int LAYER>
__global__ __launch_bounds__(512) void lstm_rec(const float* __restrict__ Whh)
{
    extern __shared__ __align__(16) float sm[];
    float* Wsm = sm;                 // 32 x 1028 (tf32)
    float* Gsm = sm + 32 * 1028;     // 4 slices x 64 x 36

    const int tid = threadIdx.x, lane = tid & 31, w = tid >> 5;
    const int g = lane >> 2, tq = lane & 3;
    const int wm = w & 1;            // batch half
    const int wk = w >> 1;           // 0..7 : k-split
    const int j0 = blockIdx.x * 8;

    // load 32 weight rows (r = gate*8 + jj) -> SMEM as tf32, stride 1028 (conflict-free)
    #pragma unroll
    for (int i = 0; i < 16; i++) {
        int fi = tid + i * 512;               // float4 index 0..8191
        int r = fi >> 8, c4 = fi & 255;
        int gate = r >> 3, jj = r & 7;
        float4 v = *(const float4*)(Whh + (size_t)(gate * HID + j0 + jj) * HID + c4 * 4);
        *(float4*)(Wsm + r * 1028 + c4 * 4) =
            make_float4(f2tf(v.x), f2tf(v.y), f2tf(v.z), f2tf(v.w));
    }

    const int ejj = tid & 7, eb = tid >> 3;   // elementwise mapping: all 512 threads
    // producer store slot (k = j0 + ejj -> kt = blockIdx.x, half = ejj>>2, tq = ejj&3)
    const size_t hslot = (size_t)blockIdx.x * 512 + (ejj >> 2) * 256 + eb * 4 + (ejj & 3);
    float cst = 0.0f;                         // cell state in registers
    __syncthreads();

    for (int t = 0; t < T_SEQ; t++) {
        const float* hb = g_hfrag[t & 1];
        // prefetch xg for the elementwise phase (hidden behind the mma body)
        const float* xgp = g_xg + ((size_t)t * BATCH + eb) * 4096 + j0 + ejj;
        float x0 = __ldcs(xgp);
        float x1 = __ldcs(xgp + 1024);
        float x2 = __ldcs(xgp + 2048);
        float x3 = __ldcs(xgp + 3072);

        float acc[2][4][4] = {};
        #pragma unroll 4
        for (int i = 0; i < 16; i++) {
            int kt = wk * 16 + i;             // 0..127
            uint32_t a[2][4];
            #pragma unroll
            for (int am = 0; am < 2; am++) {
                int mb = wm * 32 + am * 16;
                const float* p = hb + (size_t)kt * 512 + (mb + g) * 4 + tq;
                a[am][0] = __float_as_uint(__ldcg(p));         // h[kt*8+tq][mb+g]
                a[am][1] = __float_as_uint(__ldcg(p + 32));    // m+8
                a[am][2] = __float_as_uint(__ldcg(p + 256));   // k+4
                a[am][3] = __float_as_uint(__ldcg(p + 288));   // m+8, k+4
            }
            int kk = kt * 8 + tq;
            #pragma unroll
            for (int c = 0; c < 4; c++) {
                int r = c * 8 + g;            // gate-row 0..31
                uint32_t b[2];
                b[0] = __float_as_uint(Wsm[r * 1028 + kk]);
                b[1] = __float_as_uint(Wsm[r * 1028 + kk + 4]);
                mma_tf32(acc[0][c], a[0], b);
                mma_tf32(acc[1][c], a[1], b);
            }
        }

        // reduce 8 k-partials -> 4 slices, 2 rounds
        {
            float* Gs = Gsm + (wk >> 1) * (64 * 36);
            #pragma unroll
            for (int rd = 0; rd < 2; rd++) {
                if ((wk & 1) == rd) {
                    #pragma unroll
                    for (int am = 0; am < 2; am++) {
                        int m = wm * 32 + am * 16 + g;
                        #pragma unroll
                        for (int c = 0; c < 4; c++) {
                            int n = c * 8 + 2 * tq;
                            float2* p0 = (float2*)(Gs + m * 36 + n);
                            float2* p1 = (float2*)(Gs + (m + 8) * 36 + n);
                            if (rd == 0) {
                                *p0 = make_float2(acc[am][c][0], acc[am][c][1]);
                                *p1 = make_float2(acc[am][c][2], acc[am][c][3]);
                            } else {
                                float2 v0 = *p0, v1 = *p1;
                                *p0 = make_float2(v0.x + acc[am][c][0], v0.y + acc[am][c][1]);
                                *p1 = make_float2(v1.x + acc[am][c][2], v1.y + acc[am][c][3]);
                            }
                        }
                    }
                }
                __syncthreads();
            }
        }

        // elementwise LSTM cell: thread = (b=eb, jj=ejj)
        {
            int gb = eb * 36 + ejj;
            const float* G0 = Gsm;
            const float* G1 = Gsm + 64 * 36;
            const float* G2 = Gsm + 2 * 64 * 36;
            const float* G3 = Gsm + 3 * 64 * 36;
            float gi = G0[gb]      + G1[gb]      + G2[gb]      + G3[gb]      + x0;
            float gf = G0[gb + 8]  + G1[gb + 8]  + G2[gb + 8]  + G3[gb + 8]  + x1;
            float gg = G0[gb + 16] + G1[gb + 16] + G2[gb + 16] + G3[gb + 16] + x2;
            float go = G0[gb + 24] + G1[gb + 24] + G2[gb + 24] + G3[gb + 24] + x3;
            gi = 1.0f / (1.0f + __expf(-gi));
            gf = 1.0f / (1.0f + __expf(-gf));
            gg = tanhf(gg);
            go = 1.0f / (1.0f + __expf(-go));
            cst = gf * cst + gi * gg;
            float h = go * tanhf(cst);
            __stcg(&g_hfrag[(t + 1) & 1][hslot], f2tf(h));   // fragment-order, tf32
            if (LAYER == 0)
                __stcg(&g_seq0[((size_t)t * BATCH + eb) * HID + j0 + ejj], h);
        }

        // grid barrier (all 128 CTAs co-resident), release/acquire semantics
        __syncthreads();
        if (tid == 0) {
            asm volatile("red.release.gpu.global.add.u32 [%0], %1;"
                         :: "l"(&g_bar), "r"(1u) : "memory");
            unsigned target = (unsigned)(t + 1) * NCTA;
            unsigned v;
            do {
                asm volatile("ld.acquire.gpu.global.u32 %0, [%1];"
                             : "=r"(v) : "l"(&g_bar) : "memory");
            } while (v < target);
        }
        __syncthreads();
    }
}

// ---------------- fc head: out[b] = h_final[b][:] . Wfc + bfc ----------------
__global__ void fc_kernel(const float* __restrict__ Wfc, const float* __restrict__ bfc,
                          float* __restrict__ out)
{
    __shared__ float red[256];
    int b = blockIdx.x, tid = threadIdx.x;
    float s = 0.0f;
    for (int j = tid; j < HID; j += 256) {
        // fragment-order index for h (buffer 0 after t=511)
        size_t idx = (size_t)(j >> 3) * 512 + ((j >> 2) & 1) * 256 + b * 4 + (j & 3);
        s += g_hfrag[0][idx] * Wfc[j];
    }
    red[tid] = s; __syncthreads();
    for (int st = 128; st > 0; st >>= 1) {
        if (tid < st) red[tid] += red[tid + st];
        __syncthreads();
    }
    if (tid == 0) out[b] = red[0] + bfc[0];
}

// ---------------- launch ----------------
extern "C" void kernel_launch(void* const* d_in, const int* in_sizes, int n_in,
                              void* d_out, int out_size)
{
    const float* x    = (const float*)d_in[0];
    const float* Wih0 = (const float*)d_in[1];
    const float* Whh0 = (const float*)d_in[2];
    const float* b0   = (const float*)d_in[3];
    const float* Wih1 = (const float*)d_in[4];
    const float* Whh1 = (const float*)d_in[5];
    const float* b1   = (const float*)d_in[6];
    const float* Wfc  = (const float*)d_in[7];
    const float* bfc  = (const float*)d_in[8];
    float* out = (float*)d_out;

    const size_t rec_smem = (size_t)(32 * 1028 + 4 * 64 * 36) * sizeof(float);
    static int attr_done = 0;
    if (!attr_done) {
        cudaFuncSetAttribute(lstm_rec<0>, cudaFuncAttributeMaxDynamicSharedMemorySize, (int)rec_smem);
        cudaFuncSetAttribute(lstm_rec<1>, cudaFuncAttributeMaxDynamicSharedMemorySize, (int)rec_smem);
        attr_done = 1;
    }

    reset_kernel<<<64, 256>>>();
    gemm_xg<0><<<dim3(32, T_SEQ / 2), 256>>>(x, Wih0, b0, DIN);
    lstm_rec<0><<<NCTA, 512, rec_smem>>>(Whh0);
    reset_kernel<<<64, 256>>>();
    gemm_xg<1><<<dim3(32, T_SEQ / 2), 256>>>(nullptr, Wih1, b1, HID);
    lstm_rec<1><<<NCTA, 512, rec_smem>>>(Whh1);
    fc_kernel<<<BATCH, 256>>>(Wfc, bfc, out);
}

// round 11
// speedup vs baseline: 1.9250x; 1.3878x over previous
#include <cuda_runtime.h>
#include <cuda_fp16.h>
#include <cstdint>
#include <cstddef>

#define T_SEQ 512
#define BATCH 64
#define DIN   256
#define HID   1024
#define NCTA  128

// ---------------- static scratch (no allocations) ----------------
__device__ __align__(16) float g_xg[(size_t)T_SEQ * BATCH * 4096];   // [t][b][4H]
__device__ __align__(16) float g_seq0[(size_t)T_SEQ * BATCH * HID];  // [t][b][k]
// h ping-pong, fp16 pairs in m16n8k16-fragment order:
// uint32 index = kt16*512 + sub*256 + m*4 + tq   (k = kt16*16 + sub*8 + 2*tq + {lo,hi}, m = batch)
__device__ __align__(16) unsigned g_hfrag16[2][(HID / 16) * 512];    // 2 x 32768 u32
__device__ unsigned g_bar;

// ---------------- helpers ----------------
__device__ __forceinline__ unsigned pack2(float x, float y) {
    __half2 h = __floats2half2_rn(x, y);
    return *reinterpret_cast<unsigned*>(&h);
}

__device__ __forceinline__ void mma_f16(float c[4], const uint32_t a[4], const uint32_t b[2]) {
    asm volatile(
        "mma.sync.aligned.m16n8k16.row.col.f32.f16.f16.f32 "
        "{%0,%1,%2,%3}, {%4,%5,%6,%7}, {%8,%9}, {%0,%1,%2,%3};"
        : "+f"(c[0]), "+f"(c[1]), "+f"(c[2]), "+f"(c[3])
        : "r"(a[0]), "r"(a[1]), "r"(a[2]), "r"(a[3]), "r"(b[0]), "r"(b[1]));
}

// ---------------- reset: zero h ping-pong + grid barrier ----------------
__global__ void reset_kernel() {
    int tid = blockIdx.x * blockDim.x + threadIdx.x;
    unsigned* hb = (unsigned*)g_hfrag16;
    for (int i = tid; i < 2 * (HID / 16) * 512; i += gridDim.x * blockDim.x) hb[i] = 0u;
    if (tid == 0) g_bar = 0u;
}

// ---------------- xg GEMM (fp16 mma, M=128: 2 timesteps per CTA) ----------------
// g_xg[t][b][n] = A_row(t,b) . W[n][:] + bias[n]
// AMODE 0: A = x [B][T][D]      (row -> x[(b*T+t)*D + k]),      K = DIN
// AMODE 1: A = g_seq0 [T][B][H] (row -> seq0[(t*B+b)*H + k]),   K = HID
template<int AMODE>
__global__ __launch_bounds__(256) void gemm_xg(
    const float* __restrict__ A, const float* __restrict__ W,
    const float* __restrict__ bias, int K)
{
    __shared__ __align__(16) unsigned Ash[128 * 20];   // half2 pairs along k, stride 20
    __shared__ __align__(16) unsigned Bsh[128 * 20];

    const int tid = threadIdx.x, lane = tid & 31, w = tid >> 5;
    const int wm = w & 1, wn = w >> 1;          // 2 x 4 warp grid
    const int t0 = blockIdx.y * 2, n0 = blockIdx.x * 128;
    const int g = lane >> 2, tq = lane & 3;

    float acc[4][4][4] = {};

    const int nchunk = K / 32;
    for (int kc = 0; kc < nchunk; kc++) {
        int k0 = kc * 32;
        __syncthreads();
        // stage A: 128 rows (2 timesteps x 64 batch) x 32 k -> fp16 pairs
        #pragma unroll
        for (int i = 0; i < 4; i++) {
            int fi = tid + i * 256; int r = fi >> 3, k4 = fi & 7;
            int tl = r >> 6, b = r & 63;
            const float* src = (AMODE == 0)
                ? (A + ((size_t)b * T_SEQ + t0 + tl) * DIN + k0 + k4 * 4)
                : (g_seq0 + ((size_t)(t0 + tl) * BATCH + b) * HID + k0 + k4 * 4);
            float4 v = *(const float4*)src;
            *(uint2*)(Ash + r * 20 + k4 * 2) =
                make_uint2(pack2(v.x, v.y), pack2(v.z, v.w));
        }
        // stage B: 128 rows x 32 k
        #pragma unroll
        for (int i = 0; i < 4; i++) {
            int fi = tid + i * 256; int r = fi >> 3, k4 = fi & 7;
            float4 v = *(const float4*)(W + (size_t)(n0 + r) * K + k0 + k4 * 4);
            *(uint2*)(Bsh + r * 20 + k4 * 2) =
                make_uint2(pack2(v.x, v.y), pack2(v.z, v.w));
        }
        __syncthreads();
        #pragma unroll
        for (int kt = 0; kt < 2; kt++) {        // two k16 tiles per 32-k chunk
            uint32_t a[4][4];
            #pragma unroll
            for (int am = 0; am < 4; am++) {
                int mb = wm * 64 + am * 16;
                a[am][0] = Ash[(mb + g) * 20 + kt * 8 + tq];
                a[am][1] = Ash[(mb + 8 + g) * 20 + kt * 8 + tq];
                a[am][2] = Ash[(mb + g) * 20 + kt * 8 + tq + 4];
                a[am][3] = Ash[(mb + 8 + g) * 20 + kt * 8 + tq + 4];
            }
            #pragma unroll
            for (int c = 0; c < 4; c++) {
                int nb = (wn * 4 + c) * 8;
                uint32_t b[2];
                b[0] = Bsh[(nb + g) * 20 + kt * 8 + tq];
                b[1] = Bsh[(nb + g) * 20 + kt * 8 + tq + 4];
                #pragma unroll
                for (int am = 0; am < 4; am++) mma_f16(acc[am][c], a[am], b);
            }
        }
    }
    // epilogue: bias + store (fp32)
    #pragma unroll
    for (int am = 0; am < 4; am++) {
        int m = wm * 64 + am * 16 + g;
        int tl = m >> 6, b = m & 63;            // m and m+8 share tl
        #pragma unroll
        for (int c = 0; c < 4; c++) {
            int n = n0 + (wn * 4 + c) * 8 + 2 * tq;
            float2 bi = *(const float2*)(bias + n);
            *(float2*)(g_xg + ((size_t)(t0 + tl) * BATCH + b) * 4096 + n) =
                make_float2(acc[am][c][0] + bi.x, acc[am][c][1] + bi.y);
            *(float2*)(g_xg + ((size_t)(t0 + tl) * BATCH + b + 8) * 4096 + n) =
                make_float2(acc[am][c][2] + bi.x, acc[am][c][3] + bi.y);
        }
    }
}

// ---------------- persistent LSTM recurrence (fp16 mma) ----------------
// 128 CTAs x 512 threads. CTA owns 8 hidden units j0..j0+7 (32 Whh rows in SMEM as fp16).
// 16 warps = wm(2: batch halves) x wk(8: k-split of 8 k16-tiles each).
// A-fragments read from g_hfrag16 (fragment-ordered fp16): 1 wavefront / 128B per LDG.
template<int LAYER>
__global__ __launch_bounds__(512) void lstm_rec(const float* __restrict__ Whh)
{
    extern __shared__ __align__(16) char smraw[];
    unsigned* Wsm = (unsigned*)smraw;                 // 32 rows x 516 half2 (stride 516)
    float* Gsm = (float*)(smraw + 32 * 516 * 4);      // 4 slices x 64 x 36

    const int tid = threadIdx.x, lane = tid & 31, w = tid >> 5;
    const int g = lane >> 2, tq = lane & 3;
    const int wm = w & 1;            // batch half
    const int wk = w >> 1;           // 0..7 : k-split
    const int j0 = blockIdx.x * 8;

    // load 32 weight rows (r = gate*8 + jj) -> SMEM as fp16 pairs, stride 516 (conflict-free)
    #pragma unroll
    for (int i = 0; i < 16; i++) {
        int fi = tid + i * 512;               // float4 index 0..8191
        int r = fi >> 8, c4 = fi & 255;
        int gate = r >> 3, jj = r & 7;
        float4 v = *(const float4*)(Whh + (size_t)(gate * HID + j0 + jj) * HID + c4 * 4);
        *(uint2*)(Wsm + r * 516 + c4 * 2) =
            make_uint2(pack2(v.x, v.y), pack2(v.z, v.w));
    }

    const int ejj = tid & 7, eb = tid >> 3;   // elementwise mapping: all 512 threads
    // producer store slot: k = j0+ejj -> kt16 = bx>>1, sub = bx&1, tq = ejj>>1, parity = ejj&1
    const size_t hslot = (size_t)(blockIdx.x >> 1) * 512 + (blockIdx.x & 1) * 256
                       + eb * 4 + (ejj >> 1);
    float cst = 0.0f;                         // cell state in registers
    __syncthreads();

    for (int t = 0; t < T_SEQ; t++) {
        const unsigned* hb = g_hfrag16[t & 1];
        // prefetch xg for the elementwise phase (hidden behind the mma body)
        const float* xgp = g_xg + ((size_t)t * BATCH + eb) * 4096 + j0 + ejj;
        float x0 = __ldcs(xgp);
        float x1 = __ldcs(xgp + 1024);
        float x2 = __ldcs(xgp + 2048);
        float x3 = __ldcs(xgp + 3072);

        float acc[2][4][4] = {};
        #pragma unroll 4
        for (int i = 0; i < 8; i++) {
            int kt = wk * 8 + i;              // k16-tile 0..63
            uint32_t a[2][4];
            #pragma unroll
            for (int am = 0; am < 2; am++) {
                int mb = wm * 32 + am * 16;
                const unsigned* p = hb + (size_t)kt * 512 + (mb + g) * 4 + tq;
                a[am][0] = __ldcg(p);         // k 0..7 of tile, m = mb+g
                a[am][1] = __ldcg(p + 32);    // m+8
                a[am][2] = __ldcg(p + 256);   // k 8..15
                a[am][3] = __ldcg(p + 288);   // m+8, k 8..15
            }
            #pragma unroll
            for (int c = 0; c < 4; c++) {
                int r = c * 8 + g;            // gate-row 0..31
                uint32_t b[2];
                b[0] = Wsm[r * 516 + kt * 8 + tq];
                b[1] = Wsm[r * 516 + kt * 8 + tq + 4];
                mma_f16(acc[0][c], a[0], b);
                mma_f16(acc[1][c], a[1], b);
            }
        }

        // reduce 8 k-partials -> 4 slices, 2 rounds
        {
            float* Gs = Gsm + (wk >> 1) * (64 * 36);
            #pragma unroll
            for (int rd = 0; rd < 2; rd++) {
                if ((wk & 1) == rd) {
                    #pragma unroll
                    for (int am = 0; am < 2; am++) {
                        int m = wm * 32 + am * 16 + g;
                        #pragma unroll
                        for (int c = 0; c < 4; c++) {
                            int n = c * 8 + 2 * tq;
                            float2* p0 = (float2*)(Gs + m * 36 + n);
                            float2* p1 = (float2*)(Gs + (m + 8) * 36 + n);
                            if (rd == 0) {
                                *p0 = make_float2(acc[am][c][0], acc[am][c][1]);
                                *p1 = make_float2(acc[am][c][2], acc[am][c][3]);
                            } else {
                                float2 v0 = *p0, v1 = *p1;
                                *p0 = make_float2(v0.x + acc[am][c][0], v0.y + acc[am][c][1]);
                                *p1 = make_float2(v1.x + acc[am][c][2], v1.y + acc[am][c][3]);
                            }
                        }
                    }
                }
                __syncthreads();
            }
        }

        // elementwise LSTM cell: thread = (b=eb, jj=ejj)
        {
            int gb = eb * 36 + ejj;
            const float* G0 = Gsm;
            const float* G1 = Gsm + 64 * 36;
            const float* G2 = Gsm + 2 * 64 * 36;
            const float* G3 = Gsm + 3 * 64 * 36;
            float gi = G0[gb]      + G1[gb]      + G2[gb]      + G3[gb]      + x0;
            float gf = G0[gb + 8]  + G1[gb + 8]  + G2[gb + 8]  + G3[gb + 8]  + x1;
            float gg = G0[gb + 16] + G1[gb + 16] + G2[gb + 16] + G3[gb + 16] + x2;
            float go = G0[gb + 24] + G1[gb + 24] + G2[gb + 24] + G3[gb + 24] + x3;
            gi = 1.0f / (1.0f + __expf(-gi));
            gf = 1.0f / (1.0f + __expf(-gf));
            gg = tanhf(gg);
            go = 1.0f / (1.0f + __expf(-go));
            cst = gf * cst + gi * gg;
            float h = go * tanhf(cst);
            // pair h with neighbor (ejj^1) and publish fp16 pair in fragment order
            float hn = __shfl_xor_sync(0xffffffffu, h, 1);
            if ((ejj & 1) == 0)
                __stcg(&g_hfrag16[(t + 1) & 1][hslot], pack2(h, hn));
            if (LAYER == 0)
                __stcg(&g_seq0[((size_t)t * BATCH + eb) * HID + j0 + ejj], h);
        }

        // grid barrier (all 128 CTAs co-resident), release/acquire semantics
        __syncthreads();
        if (tid == 0) {
            asm volatile("red.release.gpu.global.add.u32 [%0], %1;"
                         :: "l"(&g_bar), "r"(1u) : "memory");
            unsigned target = (unsigned)(t + 1) * NCTA;
            unsigned v;
            do {
                asm volatile("ld.acquire.gpu.global.u32 %0, [%1];"
                             : "=r"(v) : "l"(&g_bar) : "memory");
            } while (v < target);
        }
        __syncthreads();
    }
}

// ---------------- fc head: out[b] = h_final[b][:] . Wfc + bfc ----------------
__global__ void fc_kernel(const float* __restrict__ Wfc, const float* __restrict__ bfc,
                          float* __restrict__ out)
{
    __shared__ float red[256];
    int b = blockIdx.x, tid = threadIdx.x;
    float s = 0.0f;
    for (int j = tid; j < HID; j += 256) {
        // fragment-order fp16 index for h (buffer 0 after t=511)
        size_t idx = (size_t)(j >> 4) * 512 + ((j >> 3) & 1) * 256 + b * 4 + ((j & 7) >> 1);
        unsigned u = g_hfrag16[0][idx];
        __half2 hv = *reinterpret_cast<__half2*>(&u);
        float h = (j & 1) ? __high2float(hv) : __low2float(hv);
        s += h * Wfc[j];
    }
    red[tid] = s; __syncthreads();
    for (int st = 128; st > 0; st >>= 1) {
        if (tid < st) red[tid] += red[tid + st];
        __syncthreads();
    }
    if (tid == 0) out[b] = red[0] + bfc[0];
}

// ---------------- launch ----------------
extern "C" void kernel_launch(void* const* d_in, const int* in_sizes, int n_in,
                              void* d_out, int out_size)
{
    const float* x    = (const float*)d_in[0];
    const float* Wih0 = (const float*)d_in[1];
    const float* Whh0 = (const float*)d_in[2];
    const float* b0   = (const float*)d_in[3];
    const float* Wih1 = (const float*)d_in[4];
    const float* Whh1 = (const float*)d_in[5];
    const float* b1   = (const float*)d_in[6];
    const float* Wfc  = (const float*)d_in[7];
    const float* bfc  = (const float*)d_in[8];
    float* out = (float*)d_out;

    const size_t rec_smem = (size_t)32 * 516 * 4 + (size_t)4 * 64 * 36 * 4;  // 102912 B
    static int attr_done = 0;
    if (!attr_done) {
        cudaFuncSetAttribute(lstm_rec<0>, cudaFuncAttributeMaxDynamicSharedMemorySize, (int)rec_smem);
        cudaFuncSetAttribute(lstm_rec<1>, cudaFuncAttributeMaxDynamicSharedMemorySize, (int)rec_smem);
        attr_done = 1;
    }

    reset_kernel<<<64, 256>>>();
    gemm_xg<0><<<dim3(32, T_SEQ / 2), 256>>>(x, Wih0, b0, DIN);
    lstm_rec<0><<<NCTA, 512, rec_smem>>>(Whh0);
    reset_kernel<<<64, 256>>>();
    gemm_xg<1><<<dim3(32, T_SEQ / 2), 256>>>(nullptr, Wih1, b1, HID);
    lstm_rec<1><<<NCTA, 512, rec_smem>>>(Whh1);
    fc_kernel<<<BATCH, 256>>>(Wfc, bfc, out);
}

// round 13
// speedup vs baseline: 1.9680x; 1.0223x over previous
#include <cuda_runtime.h>
#include <cuda_fp16.h>
#include <cstdint>
#include <cstddef>

#define T_SEQ 512
#define BATCH 64
#define DIN   256
#define HID   1024
#define NCTA  128

// ---------------- static scratch (no allocations) ----------------
__device__ __align__(16) float g_xg[(size_t)T_SEQ * BATCH * 4096];   // [t][b][4H]
__device__ __align__(16) float g_seq0[(size_t)T_SEQ * BATCH * HID];  // [t][b][k]
// h ping-pong, fp16 pairs, PAIR-INTERLEAVED m16n8k16-fragment order:
// u32 slot = kt*512 + (m*4 + tq)*2 + sub   (k = kt*16 + sub*8 + tq*2 + {lo,hi}, m = batch)
// -> (a0,a2) for a given m are ADJACENT u32 (one LDG.64)
__device__ __align__(16) unsigned g_hfrag16[2][(HID / 16) * 512];    // 2 x 32768 u32
__device__ unsigned g_bar;

// ---------------- helpers ----------------
__device__ __forceinline__ unsigned pack2(float x, float y) {
    __half2 h = __floats2half2_rn(x, y);
    return *reinterpret_cast<unsigned*>(&h);
}

__device__ __forceinline__ void mma_f16(float c[4], const uint32_t a[4], const uint32_t b[2]) {
    asm volatile(
        "mma.sync.aligned.m16n8k16.row.col.f32.f16.f16.f32 "
        "{%0,%1,%2,%3}, {%4,%5,%6,%7}, {%8,%9}, {%0,%1,%2,%3};"
        : "+f"(c[0]), "+f"(c[1]), "+f"(c[2]), "+f"(c[3])
        : "r"(a[0]), "r"(a[1]), "r"(a[2]), "r"(a[3]), "r"(b[0]), "r"(b[1]));
}

// ---------------- reset: zero h ping-pong + grid barrier ----------------
__global__ void reset_kernel() {
    int tid = blockIdx.x * blockDim.x + threadIdx.x;
    unsigned* hb = (unsigned*)g_hfrag16;
    for (int i = tid; i < 2 * (HID / 16) * 512; i += gridDim.x * blockDim.x) hb[i] = 0u;
    if (tid == 0) g_bar = 0u;
}

// ---------------- xg GEMM (fp16 mma, M=128: 2 timesteps per CTA) ----------------
template<int AMODE>
__global__ __launch_bounds__(256) void gemm_xg(
    const float* __restrict__ A, const float* __restrict__ W,
    const float* __restrict__ bias, int K)
{
    __shared__ __align__(16) unsigned Ash[128 * 20];   // half2 pairs along k, stride 20
    __shared__ __align__(16) unsigned Bsh[128 * 20];

    const int tid = threadIdx.x, lane = tid & 31, w = tid >> 5;
    const int wm = w & 1, wn = w >> 1;          // 2 x 4 warp grid
    const int t0 = blockIdx.y * 2, n0 = blockIdx.x * 128;
    const int g = lane >> 2, tq = lane & 3;

    float acc[4][4][4] = {};

    const int nchunk = K / 32;
    for (int kc = 0; kc < nchunk; kc++) {
        int k0 = kc * 32;
        __syncthreads();
        #pragma unroll
        for (int i = 0; i < 4; i++) {
            int fi = tid + i * 256; int r = fi >> 3, k4 = fi & 7;
            int tl = r >> 6, b = r & 63;
            const float* src = (AMODE == 0)
                ? (A + ((size_t)b * T_SEQ + t0 + tl) * DIN + k0 + k4 * 4)
                : (g_seq0 + ((size_t)(t0 + tl) * BATCH + b) * HID + k0 + k4 * 4);
            float4 v = *(const float4*)src;
            *(uint2*)(Ash + r * 20 + k4 * 2) =
                make_uint2(pack2(v.x, v.y), pack2(v.z, v.w));
        }
        #pragma unroll
        for (int i = 0; i < 4; i++) {
            int fi = tid + i * 256; int r = fi >> 3, k4 = fi & 7;
            float4 v = *(const float4*)(W + (size_t)(n0 + r) * K + k0 + k4 * 4);
            *(uint2*)(Bsh + r * 20 + k4 * 2) =
                make_uint2(pack2(v.x, v.y), pack2(v.z, v.w));
        }
        __syncthreads();
        #pragma unroll
        for (int kt = 0; kt < 2; kt++) {
            uint32_t a[4][4];
            #pragma unroll
            for (int am = 0; am < 4; am++) {
                int mb = wm * 64 + am * 16;
                a[am][0] = Ash[(mb + g) * 20 + kt * 8 + tq];
                a[am][1] = Ash[(mb + 8 + g) * 20 + kt * 8 + tq];
                a[am][2] = Ash[(mb + g) * 20 + kt * 8 + tq + 4];
                a[am][3] = Ash[(mb + 8 + g) * 20 + kt * 8 + tq + 4];
            }
            #pragma unroll
            for (int c = 0; c < 4; c++) {
                int nb = (wn * 4 + c) * 8;
                uint32_t b[2];
                b[0] = Bsh[(nb + g) * 20 + kt * 8 + tq];
                b[1] = Bsh[(nb + g) * 20 + kt * 8 + tq + 4];
                #pragma unroll
                for (int am = 0; am < 4; am++) mma_f16(acc[am][c], a[am], b);
            }
        }
    }
    #pragma unroll
    for (int am = 0; am < 4; am++) {
        int m = wm * 64 + am * 16 + g;
        int tl = m >> 6, b = m & 63;
        #pragma unroll
        for (int c = 0; c < 4; c++) {
            int n = n0 + (wn * 4 + c) * 8 + 2 * tq;
            float2 bi = *(const float2*)(bias + n);
            *(float2*)(g_xg + ((size_t)(t0 + tl) * BATCH + b) * 4096 + n) =
                make_float2(acc[am][c][0] + bi.x, acc[am][c][1] + bi.y);
            *(float2*)(g_xg + ((size_t)(t0 + tl) * BATCH + b + 8) * 4096 + n) =
                make_float2(acc[am][c][2] + bi.x, acc[am][c][3] + bi.y);
        }
    }
}

// ---------------- persistent LSTM recurrence (fp16 mma) ----------------
// 128 CTAs x 512 threads. CTA owns 8 hidden units (32 gate rows).
// Whh kept in SMEM in B-FRAGMENT order: Bsm[(kt*4+c)*32 + lane] = uint2 (b0=sub0, b1=sub1).
// A-fragments: two LDG.64 per m-tile from pair-interleaved g_hfrag16.
template<int LAYER>
__global__ __launch_bounds__(512) void lstm_rec(const float* __restrict__ Whh)
{
    extern __shared__ __align__(16) char smraw[];
    uint2* Bsm = (uint2*)smraw;                       // 64kt x 4c x 32lane uint2 = 64 KB
    float* Gsm = (float*)(smraw + 65536);             // 4 slices x 64 x 36

    const int tid = threadIdx.x, lane = tid & 31, w = tid >> 5;
    const int g = lane >> 2, tq = lane & 3;
    const int wm = w & 1;            // batch half
    const int wk = w >> 1;           // 0..7 : k-split (8 k16-tiles each)
    const int j0 = blockIdx.x * 8;

    // load 32 weight rows -> SMEM directly in B-fragment order
    unsigned* Wsm32 = (unsigned*)smraw;
    #pragma unroll
    for (int i = 0; i < 16; i++) {
        int fi = tid + i * 512;               // float4 index 0..8191
        int r = fi >> 8, c4 = fi & 255;       // r = gate*8+jj ; k0 = c4*4
        int gate = r >> 3, jj = r & 7;
        float4 v = *(const float4*)(Whh + (size_t)(gate * HID + j0 + jj) * HID + c4 * 4);
        int kt = c4 >> 2, sub = (c4 >> 1) & 1, tq0 = (c4 & 1) * 2;
        int base = ((kt * 4 + gate) * 32 + jj * 4 + tq0) * 2 + sub;
        Wsm32[base]     = pack2(v.x, v.y);
        Wsm32[base + 2] = pack2(v.z, v.w);
    }

    const int ejj = tid & 7, eb = tid >> 3;   // elementwise mapping: all 512 threads
    // producer u32 slot: k = j0+ejj -> kt = bx>>1, sub = bx&1, tq = ejj>>1
    const size_t hslot = (size_t)(blockIdx.x >> 1) * 512 + ((size_t)eb * 4 + (ejj >> 1)) * 2
                       + (blockIdx.x & 1);
    float cst = 0.0f;
    __syncthreads();

    // prefetch xg for t=0
    const float* xgp = g_xg + (size_t)eb * 4096 + j0 + ejj;
    float x0 = __ldcs(xgp), x1 = __ldcs(xgp + 1024),
          x2 = __ldcs(xgp + 2048), x3 = __ldcs(xgp + 3072);

    for (int t = 0; t < T_SEQ; t++) {
        const uint2* hb2 = (const uint2*)g_hfrag16[t & 1];

        float acc[2][4][4] = {};
        #pragma unroll 4
        for (int i = 0; i < 8; i++) {
            int kt = wk * 8 + i;              // k16-tile 0..63
            uint32_t a[2][4];
            #pragma unroll
            for (int am = 0; am < 2; am++) {
                int mb = wm * 32 + am * 16;
                uint2 u0 = __ldcg(hb2 + (size_t)kt * 256 + (mb + g) * 4 + tq);
                uint2 u1 = __ldcg(hb2 + (size_t)kt * 256 + (mb + 8 + g) * 4 + tq);
                a[am][0] = u0.x; a[am][1] = u1.x; a[am][2] = u0.y; a[am][3] = u1.y;
            }
            #pragma unroll
            for (int c = 0; c < 4; c++) {
                uint2 bb = Bsm[(kt * 4 + c) * 32 + lane];
                uint32_t b[2] = { bb.x, bb.y };
                mma_f16(acc[0][c], a[0], b);
                mma_f16(acc[1][c], a[1], b);
            }
        }

        // reduce 8 k-partials -> 4 slices, 2 rounds
        {
            float* Gs = Gsm + (wk >> 1) * (64 * 36);
            #pragma unroll
            for (int rd = 0; rd < 2; rd++) {
                if ((wk & 1) == rd) {
                    #pragma unroll
                    for (int am = 0; am < 2; am++) {
                        int m = wm * 32 + am * 16 + g;
                        #pragma unroll
                        for (int c = 0; c < 4; c++) {
                            int n = c * 8 + 2 * tq;
                            float2* p0 = (float2*)(Gs + m * 36 + n);
                            float2* p1 = (float2*)(Gs + (m + 8) * 36 + n);
                            if (rd == 0) {
                                *p0 = make_float2(acc[am][c][0], acc[am][c][1]);
                                *p1 = make_float2(acc[am][c][2], acc[am][c][3]);
                            } else {
                                float2 v0 = *p0, v1 = *p1;
                                *p0 = make_float2(v0.x + acc[am][c][0], v0.y + acc[am][c][1]);
                                *p1 = make_float2(v1.x + acc[am][c][2], v1.y + acc[am][c][3]);
                            }
                        }
                    }
                }
                __syncthreads();
            }
        }

        // elementwise LSTM cell: thread = (b=eb, jj=ejj)
        {
            int gb = eb * 36 + ejj;
            const float* G0 = Gsm;
            const float* G1 = Gsm + 64 * 36;
            const float* G2 = Gsm + 2 * 64 * 36;
            const float* G3 = Gsm + 3 * 64 * 36;
            float gi = G0[gb]      + G1[gb]      + G2[gb]      + G3[gb]      + x0;
            float gf = G0[gb + 8]  + G1[gb + 8]  + G2[gb + 8]  + G3[gb + 8]  + x1;
            float gg = G0[gb + 16] + G1[gb + 16] + G2[gb + 16] + G3[gb + 16] + x2;
            float go = G0[gb + 24] + G1[gb + 24] + G2[gb + 24] + G3[gb + 24] + x3;
            gi = 1.0f / (1.0f + __expf(-gi));
            gf = 1.0f / (1.0f + __expf(-gf));
            gg = tanhf(gg);
            go = 1.0f / (1.0f + __expf(-go));
            cst = gf * cst + gi * gg;
            float h = go * tanhf(cst);
            float hn = __shfl_xor_sync(0xffffffffu, h, 1);
            if ((ejj & 1) == 0)
                __stcg(&g_hfrag16[(t + 1) & 1][hslot], pack2(h, hn));
            if (LAYER == 0)
                __stcg(&g_seq0[((size_t)t * BATCH + eb) * HID + j0 + ejj], h);
        }

        // grid barrier; prefetch next xg between arrive and wait
        __syncthreads();
        if (tid == 0) {
            asm volatile("red.release.gpu.global.add.u32 [%0], %1;"
                         :: "l"(&g_bar), "r"(1u) : "memory");
        }
        {
            int tn = (t + 1 < T_SEQ) ? t + 1 : t;   // clamp (last iter values unused)
            const float* xq = g_xg + ((size_t)tn * BATCH + eb) * 4096 + j0 + ejj;
            x0 = __ldcs(xq); x1 = __ldcs(xq + 1024);
            x2 = __ldcs(xq + 2048); x3 = __ldcs(xq + 3072);
        }
        if (tid == 0) {
            unsigned target = (unsigned)(t + 1) * NCTA + (LAYER ? T_SEQ * NCTA : 0);
            unsigned v;
            do {
                asm volatile("ld.acquire.gpu.global.u32 %0, [%1];"
                             : "=r"(v) : "l"(&g_bar) : "memory");
            } while (v < target);
        }
        __syncthreads();
    }
}

// ---------------- fc head: out[b] = h_final[b][:] . Wfc + bfc ----------------
__global__ void fc_kernel(const float* __restrict__ Wfc, const float* __restrict__ bfc,
                          float* __restrict__ out)
{
    __shared__ float red[256];
    int b = blockIdx.x, tid = threadIdx.x;
    float s = 0.0f;
    for (int j = tid; j < HID; j += 256) {
        int kt = j >> 4, sub = (j >> 3) & 1, tq = (j >> 1) & 3;
        size_t idx = (size_t)kt * 512 + ((size_t)b * 4 + tq) * 2 + sub;
        unsigned u = g_hfrag16[0][idx];
        __half2 hv = *reinterpret_cast<__half2*>(&u);
        float h = (j & 1) ? __high2float(hv) : __low2float(hv);
        s += h * Wfc[j];
    }
    red[tid] = s; __syncthreads();
    for (int st = 128; st > 0; st >>= 1) {
        if (tid < st) red[tid] += red[tid + st];
        __syncthreads();
    }
    if (tid == 0) out[b] = red[0] + bfc[0];
}

// ---------------- launch ----------------
extern "C" void kernel_launch(void* const* d_in, const int* in_sizes, int n_in,
                              void* d_out, int out_size)
{
    const float* x    = (const float*)d_in[0];
    const float* Wih0 = (const float*)d_in[1];
    const float* Whh0 = (const float*)d_in[2];
    const float* b0   = (const float*)d_in[3];
    const float* Wih1 = (const float*)d_in[4];
    const float* Whh1 = (const float*)d_in[5];
    const float* b1   = (const float*)d_in[6];
    const float* Wfc  = (const float*)d_in[7];
    const float* bfc  = (const float*)d_in[8];
    float* out = (float*)d_out;

    const size_t rec_smem = 65536 + (size_t)4 * 64 * 36 * 4;   // 102400 B
    static int attr_done = 0;
    if (!attr_done) {
        cudaFuncSetAttribute(lstm_rec<0>, cudaFuncAttributeMaxDynamicSharedMemorySize, (int)rec_smem);
        cudaFuncSetAttribute(lstm_rec<1>, cudaFuncAttributeMaxDynamicSharedMemorySize, (int)rec_smem);
        attr_done = 1;
    }

    reset_kernel<<<64, 256>>>();
    gemm_xg<0><<<dim3(32, T_SEQ / 2), 256>>>(x, Wih0, b0, DIN);
    lstm_rec<0><<<NCTA, 512, rec_smem>>>(Whh0);
    gemm_xg<1><<<dim3(32, T_SEQ / 2), 256>>>(nullptr, Wih1, b1, HID);
    lstm_rec<1><<<NCTA, 512, rec_smem>>>(Whh1);   // barrier counter continues from T_SEQ*NCTA
    fc_kernel<<<BATCH, 256>>>(Wfc, bfc, out);
}

// round 15
// speedup vs baseline: 2.3125x; 1.1750x over previous
#include <cuda_runtime.h>
#include <cuda_fp16.h>
#include <cstdint>
#include <cstddef>

#define T_SEQ 512
#define BATCH 64
#define DIN   256
#define HID   1024
#define NREC  256   // recurrence CTAs (2 per SM)

// ---------------- static scratch (no allocations) ----------------
__device__ __align__(16) float g_xg[(size_t)T_SEQ * BATCH * 4096];   // [t][b][4H]
__device__ __align__(16) float g_seq0[(size_t)T_SEQ * BATCH * HID];  // [t][b][k]
// h ping-pong, fp16 pairs, PAIR-INTERLEAVED m16n8k16-fragment order:
// u32 slot = kt*512 + (m*4 + tq)*2 + sub   (k = kt*16 + sub*8 + tq*2 + {lo,hi}, m = batch)
__device__ __align__(16) unsigned g_hfrag16[2][(HID / 16) * 512];    // 2 x 32768 u32
__device__ unsigned g_bar;

// ---------------- helpers ----------------
__device__ __forceinline__ unsigned pack2(float x, float y) {
    __half2 h = __floats2half2_rn(x, y);
    return *reinterpret_cast<unsigned*>(&h);
}

__device__ __forceinline__ void mma_f16(float c[4], const uint32_t a[4], const uint32_t b[2]) {
    asm volatile(
        "mma.sync.aligned.m16n8k16.row.col.f32.f16.f16.f32 "
        "{%0,%1,%2,%3}, {%4,%5,%6,%7}, {%8,%9}, {%0,%1,%2,%3};"
        : "+f"(c[0]), "+f"(c[1]), "+f"(c[2]), "+f"(c[3])
        : "r"(a[0]), "r"(a[1]), "r"(a[2]), "r"(a[3]), "r"(b[0]), "r"(b[1]));
}

// ---------------- reset: zero h ping-pong + grid barrier ----------------
__global__ void reset_kernel() {
    int tid = blockIdx.x * blockDim.x + threadIdx.x;
    unsigned* hb = (unsigned*)g_hfrag16;
    for (int i = tid; i < 2 * (HID / 16) * 512; i += gridDim.x * blockDim.x) hb[i] = 0u;
    if (tid == 0) g_bar = 0u;
}

// ---------------- xg GEMM (fp16 mma, M=128: 2 timesteps per CTA) ----------------
template<int AMODE>
__global__ __launch_bounds__(256) void gemm_xg(
    const float* __restrict__ A, const float* __restrict__ W,
    const float* __restrict__ bias, int K)
{
    __shared__ __align__(16) unsigned Ash[128 * 20];   // half2 pairs along k, stride 20
    __shared__ __align__(16) unsigned Bsh[128 * 20];

    const int tid = threadIdx.x, lane = tid & 31, w = tid >> 5;
    const int wm = w & 1, wn = w >> 1;          // 2 x 4 warp grid
    const int t0 = blockIdx.y * 2, n0 = blockIdx.x * 128;
    const int g = lane >> 2, tq = lane & 3;

    float acc[4][4][4] = {};

    const int nchunk = K / 32;
    for (int kc = 0; kc < nchunk; kc++) {
        int k0 = kc * 32;
        __syncthreads();
        #pragma unroll
        for (int i = 0; i < 4; i++) {
            int fi = tid + i * 256; int r = fi >> 3, k4 = fi & 7;
            int tl = r >> 6, b = r & 63;
            const float* src = (AMODE == 0)
                ? (A + ((size_t)b * T_SEQ + t0 + tl) * DIN + k0 + k4 * 4)
                : (g_seq0 + ((size_t)(t0 + tl) * BATCH + b) * HID + k0 + k4 * 4);
            float4 v = *(const float4*)src;
            *(uint2*)(Ash + r * 20 + k4 * 2) =
                make_uint2(pack2(v.x, v.y), pack2(v.z, v.w));
        }
        #pragma unroll
        for (int i = 0; i < 4; i++) {
            int fi = tid + i * 256; int r = fi >> 3, k4 = fi & 7;
            float4 v = *(const float4*)(W + (size_t)(n0 + r) * K + k0 + k4 * 4);
            *(uint2*)(Bsh + r * 20 + k4 * 2) =
                make_uint2(pack2(v.x, v.y), pack2(v.z, v.w));
        }
        __syncthreads();
        #pragma unroll
        for (int kt = 0; kt < 2; kt++) {
            uint32_t a[4][4];
            #pragma unroll
            for (int am = 0; am < 4; am++) {
                int mb = wm * 64 + am * 16;
                a[am][0] = Ash[(mb + g) * 20 + kt * 8 + tq];
                a[am][1] = Ash[(mb + 8 + g) * 20 + kt * 8 + tq];
                a[am][2] = Ash[(mb + g) * 20 + kt * 8 + tq + 4];
                a[am][3] = Ash[(mb + 8 + g) * 20 + kt * 8 + tq + 4];
            }
            #pragma unroll
            for (int c = 0; c < 4; c++) {
                int nb = (wn * 4 + c) * 8;
                uint32_t b[2];
                b[0] = Bsh[(nb + g) * 20 + kt * 8 + tq];
                b[1] = Bsh[(nb + g) * 20 + kt * 8 + tq + 4];
                #pragma unroll
                for (int am = 0; am < 4; am++) mma_f16(acc[am][c], a[am], b);
            }
        }
    }
    #pragma unroll
    for (int am = 0; am < 4; am++) {
        int m = wm * 64 + am * 16 + g;
        int tl = m >> 6, b = m & 63;
        #pragma unroll
        for (int c = 0; c < 4; c++) {
            int n = n0 + (wn * 4 + c) * 8 + 2 * tq;
            float2 bi = *(const float2*)(bias + n);
            *(float2*)(g_xg + ((size_t)(t0 + tl) * BATCH + b) * 4096 + n) =
                make_float2(acc[am][c][0] + bi.x, acc[am][c][1] + bi.y);
            *(float2*)(g_xg + ((size_t)(t0 + tl) * BATCH + b + 8) * 4096 + n) =
                make_float2(acc[am][c][2] + bi.x, acc[am][c][3] + bi.y);
        }
    }
}

// ---------------- persistent LSTM recurrence (fp16 mma, 2 CTAs/SM) ----------------
// 256 CTAs x 256 threads. CTA owns 4 hidden units j0..j0+3 -> 16 gate rows (nrow = gate*4+jj).
// 8 warps = wm(2: batch halves) x wk(4: k-split of 16 k16-tiles each).
// Whh in SMEM in B-fragment order: Bsm[(kt*2 + c)*32 + lane] = uint2 (b0=sub0, b1=sub1).
template<int LAYER>
__global__ __launch_bounds__(256, 2) void lstm_rec(const float* __restrict__ Whh)
{
    extern __shared__ __align__(16) char smraw[];
    uint2* Bsm = (uint2*)smraw;                       // 64kt x 2c x 32lane uint2 = 32 KB
    float* Gsm = (float*)(smraw + 32768);             // 4 slices x 64 x 20

    const int tid = threadIdx.x, lane = tid & 31, w = tid >> 5;
    const int g = lane >> 2, tq = lane & 3;
    const int wm = w & 1;            // batch half
    const int wk = w >> 1;           // 0..3 : k-split (16 k16-tiles each)
    const int bx = blockIdx.x;
    const int j0 = bx * 4;

    // load 16 weight rows (nrow = gate*4 + jj) -> SMEM in B-fragment order
    unsigned* Wsm32 = (unsigned*)smraw;
    #pragma unroll
    for (int i = 0; i < 16; i++) {
        int fi = tid + i * 256;               // float4 index 0..4095
        int r = fi >> 8, c4 = fi & 255;       // r = nrow = gate*4+jj ; k0 = c4*4
        int gate = r >> 2, jj = r & 3;
        float4 v = *(const float4*)(Whh + (size_t)(gate * HID + j0 + jj) * HID + c4 * 4);
        int kt = c4 >> 2, sub = (c4 >> 1) & 1, tq0 = (c4 & 1) * 2;
        int base = ((kt * 2 + (r >> 3)) * 32 + (r & 7) * 4 + tq0) * 2 + sub;
        Wsm32[base]     = pack2(v.x, v.y);
        Wsm32[base + 2] = pack2(v.z, v.w);
    }

    const int ejj = tid & 3, eb = tid >> 2;   // elementwise mapping: 256 threads = 64b x 4jj
    // producer u32 slot for k = j0+ejj:
    const int ktp = bx >> 2, subp = (bx >> 1) & 1, tqp = (bx & 1) * 2 + (ejj >> 1);
    const size_t hslot = (size_t)ktp * 512 + ((size_t)eb * 4 + tqp) * 2 + subp;
    float cst = 0.0f;
    __syncthreads();

    // prefetch xg for t=0
    {
        const float* xq = g_xg + (size_t)eb * 4096 + j0 + ejj;
        (void)xq;
    }
    const float* xgp = g_xg + (size_t)eb * 4096 + j0 + ejj;
    float x0 = __ldcs(xgp), x1 = __ldcs(xgp + 1024),
          x2 = __ldcs(xgp + 2048), x3 = __ldcs(xgp + 3072);

    for (int t = 0; t < T_SEQ; t++) {
        const uint2* hb2 = (const uint2*)g_hfrag16[t & 1];

        float acc[2][2][4] = {};
        #pragma unroll 4
        for (int i = 0; i < 16; i++) {
            int kt = wk * 16 + i;             // k16-tile 0..63
            uint32_t a[2][4];
            #pragma unroll
            for (int am = 0; am < 2; am++) {
                int mb = wm * 32 + am * 16;
                uint2 u0 = __ldcg(hb2 + (size_t)kt * 256 + (mb + g) * 4 + tq);
                uint2 u1 = __ldcg(hb2 + (size_t)kt * 256 + (mb + 8 + g) * 4 + tq);
                a[am][0] = u0.x; a[am][1] = u1.x; a[am][2] = u0.y; a[am][3] = u1.y;
            }
            #pragma unroll
            for (int c = 0; c < 2; c++) {
                uint2 bb = Bsm[(kt * 2 + c) * 32 + lane];
                uint32_t b[2] = { bb.x, bb.y };
                mma_f16(acc[0][c], a[0], b);
                mma_f16(acc[1][c], a[1], b);
            }
        }

        // single-round reduce: each k-split warp writes its own slice
        {
            float* Gs = Gsm + wk * (64 * 20);
            #pragma unroll
            for (int am = 0; am < 2; am++) {
                int m = wm * 32 + am * 16 + g;
                #pragma unroll
                for (int c = 0; c < 2; c++) {
                    int n = c * 8 + 2 * tq;
                    *(float2*)(Gs + m * 20 + n)       = make_float2(acc[am][c][0], acc[am][c][1]);
                    *(float2*)(Gs + (m + 8) * 20 + n) = make_float2(acc[am][c][2], acc[am][c][3]);
                }
            }
        }
        __syncthreads();

        // elementwise LSTM cell: thread = (b=eb, jj=ejj); sum 4 slices
        {
            int gb = eb * 20 + ejj;           // + gate*4
            float gi = x0, gf = x1, gg = x2, go = x3;
            #pragma unroll
            for (int s = 0; s < 4; s++) {
                const float* Gs = Gsm + s * (64 * 20);
                gi += Gs[gb];
                gf += Gs[gb + 4];
                gg += Gs[gb + 8];
                go += Gs[gb + 12];
            }
            gi = 1.0f / (1.0f + __expf(-gi));
            gf = 1.0f / (1.0f + __expf(-gf));
            gg = tanhf(gg);
            go = 1.0f / (1.0f + __expf(-go));
            cst = gf * cst + gi * gg;
            float h = go * tanhf(cst);
            float hn = __shfl_xor_sync(0xffffffffu, h, 1);
            if ((ejj & 1) == 0)
                __stcg(&g_hfrag16[(t + 1) & 1][hslot], pack2(h, hn));
            if (LAYER == 0)
                __stcg(&g_seq0[((size_t)t * BATCH + eb) * HID + j0 + ejj], h);
        }

        // grid barrier (256 CTAs, 2/SM co-resident); prefetch next xg inside
        __syncthreads();
        if (tid == 0) {
            asm volatile("red.release.gpu.global.add.u32 [%0], %1;"
                         :: "l"(&g_bar), "r"(1u) : "memory");
        }
        {
            int tn = (t + 1 < T_SEQ) ? t + 1 : t;   // clamp (last iter values unused)
            const float* xq = g_xg + ((size_t)tn * BATCH + eb) * 4096 + j0 + ejj;
            x0 = __ldcs(xq); x1 = __ldcs(xq + 1024);
            x2 = __ldcs(xq + 2048); x3 = __ldcs(xq + 3072);
        }
        if (tid == 0) {
            unsigned target = (unsigned)(t + 1) * NREC + (LAYER ? (unsigned)T_SEQ * NREC : 0u);
            unsigned v;
            do {
                asm volatile("ld.acquire.gpu.global.u32 %0, [%1];"
                             : "=r"(v) : "l"(&g_bar) : "memory");
            } while (v < target);
        }
        __syncthreads();
    }
}

// ---------------- fc head: out[b] = h_final[b][:] . Wfc + bfc ----------------
__global__ void fc_kernel(const float* __restrict__ Wfc, const float* __restrict__ bfc,
                          float* __restrict__ out)
{
    __shared__ float red[256];
    int b = blockIdx.x, tid = threadIdx.x;
    float s = 0.0f;
    for (int j = tid; j < HID; j += 256) {
        int kt = j >> 4, sub = (j >> 3) & 1, tq = (j >> 1) & 3;
        size_t idx = (size_t)kt * 512 + ((size_t)b * 4 + tq) * 2 + sub;
        unsigned u = g_hfrag16[0][idx];
        __half2 hv = *reinterpret_cast<__half2*>(&u);
        float h = (j & 1) ? __high2float(hv) : __low2float(hv);
        s += h * Wfc[j];
    }
    red[tid] = s; __syncthreads();
    for (int st = 128; st > 0; st >>= 1) {
        if (tid < st) red[tid] += red[tid + st];
        __syncthreads();
    }
    if (tid == 0) out[b] = red[0] + bfc[0];
}

// ---------------- launch ----------------
extern "C" void kernel_launch(void* const* d_in, const int* in_sizes, int n_in,
                              void* d_out, int out_size)
{
    const float* x    = (const float*)d_in[0];
    const float* Wih0 = (const float*)d_in[1];
    const float* Whh0 = (const float*)d_in[2];
    const float* b0   = (const float*)d_in[3];
    const float* Wih1 = (const float*)d_in[4];
    const float* Whh1 = (const float*)d_in[5];
    const float* b1   = (const float*)d_in[6];
    const float* Wfc  = (const float*)d_in[7];
    const float* bfc  = (const float*)d_in[8];
    float* out = (float*)d_out;

    const size_t rec_smem = 32768 + (size_t)4 * 64 * 20 * 4;   // 53248 B (2 CTAs/SM)
    static int attr_done = 0;
    if (!attr_done) {
        cudaFuncSetAttribute(lstm_rec<0>, cudaFuncAttributeMaxDynamicSharedMemorySize, (int)rec_smem);
        cudaFuncSetAttribute(lstm_rec<1>, cudaFuncAttributeMaxDynamicSharedMemorySize, (int)rec_smem);
        attr_done = 1;
    }

    reset_kernel<<<64, 256>>>();
    gemm_xg<0><<<dim3(32, T_SEQ / 2), 256>>>(x, Wih0, b0, DIN);
    lstm_rec<0><<<NREC, 256, rec_smem>>>(Whh0);
    gemm_xg<1><<<dim3(32, T_SEQ / 2), 256>>>(nullptr, Wih1, b1, HID);
    lstm_rec<1><<<NREC, 256, rec_smem>>>(Whh1);   // barrier counter continues from T_SEQ*NREC
    fc_kernel<<<BATCH, 256>>>(Wfc, bfc, out);
}